// round 15
// baseline (speedup 1.0000x reference)
#include <cuda_runtime.h>
#include <cstdint>

// StochasticAttention collapses algebraically:
//   attention[b,q,v] = sum_f x[b,v,f] * (sum_d w_value[d,f])   (independent of q)
//
// PDL pair: k_wsum (32 blocks) overlaps k_fused's x prefetch. Round-15 change:
// BOTH x loads and out stores use L2::evict_last. Working set 64+64=128MB vs
// ~126MB L2 — near-total residency in steady state turns the replay loop into
// an L2-bandwidth problem instead of a DRAM one.

#define FDIM 1024
#define BDIM 16
#define DDIM 64

__device__ __align__(16) float g_wsum[FDIM];

struct U4 { uint64_t a, b, c, d; };

__device__ __forceinline__ U4 ldg_pin32(const void* p) {
    U4 v;
    asm volatile("ld.global.nc.L2::evict_last.v4.b64 {%0,%1,%2,%3}, [%4];"
                 : "=l"(v.a), "=l"(v.b), "=l"(v.c), "=l"(v.d) : "l"(p));
    return v;
}
__device__ __forceinline__ void stg_pin32(void* p, float4 v0, float4 v1) {
    uint64_t a = ((uint64_t)__float_as_uint(v0.y) << 32) | __float_as_uint(v0.x);
    uint64_t b = ((uint64_t)__float_as_uint(v0.w) << 32) | __float_as_uint(v0.z);
    uint64_t c = ((uint64_t)__float_as_uint(v1.y) << 32) | __float_as_uint(v1.x);
    uint64_t d = ((uint64_t)__float_as_uint(v1.w) << 32) | __float_as_uint(v1.z);
    asm volatile("st.global.L2::evict_last.v4.b64 [%0], {%1,%2,%3,%4};"
                 :: "l"(p), "l"(a), "l"(b), "l"(c), "l"(d) : "memory");
}
__device__ __forceinline__ float flo(uint64_t u) { return __uint_as_float((unsigned)u); }
__device__ __forceinline__ float fhi(uint64_t u) { return __uint_as_float((unsigned)(u >> 32)); }

// ---- wsum = column-sum of w_value [D, F] (32 blocks, parallel) ----
__global__ void k_wsum(const float* __restrict__ w_value) {
    __shared__ __align__(16) float4 part[32][8];
    const int col  = threadIdx.x & 7;
    const int dg   = threadIdx.x >> 3;
    const int gcol = blockIdx.x * 8 + col;
    const float4* w4 = reinterpret_cast<const float4*>(w_value);
    float4 a = w4[(size_t)(2 * dg)     * (FDIM / 4) + gcol];
    float4 b = w4[(size_t)(2 * dg + 1) * (FDIM / 4) + gcol];
    float4 s;
    s.x = a.x + b.x; s.y = a.y + b.y; s.z = a.z + b.z; s.w = a.w + b.w;
    part[dg][col] = s;
    __syncthreads();
    if (threadIdx.x < 8) {
        float4 acc = part[0][threadIdx.x];
#pragma unroll
        for (int k = 1; k < 32; ++k) {
            float4 p = part[k][threadIdx.x];
            acc.x += p.x; acc.y += p.y; acc.z += p.z; acc.w += p.w;
        }
        reinterpret_cast<float4*>(g_wsum)[blockIdx.x * 8 + threadIdx.x] = acc;
    }
    __threadfence();
    cudaTriggerProgrammaticLaunchCompletion();
}

__global__ __launch_bounds__(1024, 1)
void k_fused(const float* __restrict__ x, float* __restrict__ out) {
    __shared__ __align__(16) float4 s_wsum[FDIM / 4];  // 4 KB
    __shared__ __align__(16) float  s_row[4][32];

    const int tid  = threadIdx.x;
    const int warp = tid >> 5;
    const int lane = tid & 31;
    const int b     = blockIdx.x >> 3;
    const int chunk = blockIdx.x & 7;

    const char* xbytes = reinterpret_cast<const char*>(x);
    const unsigned rowbase = ((unsigned)b << 10) + ((unsigned)chunk << 7);

    // ---- Prefetch sub-chunk 0 BEFORE the grid dependency sync (overlaps k_wsum) ----
    U4 a[4];
    {
        const char* xr = xbytes + (size_t)(rowbase + warp) * (FDIM * 4);
#pragma unroll
        for (int t = 0; t < 4; ++t) a[t] = ldg_pin32(xr + (t * 32 + lane) * 32);
    }

    // ---- Wait for k_wsum, then pull 4KB g_wsum into shared ----
    cudaGridDependencySynchronize();
    if (tid < FDIM / 4)
        s_wsum[tid] = reinterpret_cast<const float4*>(g_wsum)[tid];
    __syncthreads();

    // ---- Pipelined sub-chunks: 32 rows each ----
    float4* out4 = reinterpret_cast<float4*>(out);
    const int qoff = lane >> 2;
    const int col2 = lane & 3;
    const unsigned obase = ((unsigned)b << 18) + ((unsigned)chunk << 5);

#pragma unroll
    for (int s = 0; s < 4; ++s) {
        float acc = 0.f;
#pragma unroll
        for (int t = 0; t < 4; ++t) {
            const int c = t * 32 + lane;
            float4 w0 = s_wsum[2 * c];
            float4 w1 = s_wsum[2 * c + 1];
            acc += flo(a[t].a) * w0.x + fhi(a[t].a) * w0.y
                 + flo(a[t].b) * w0.z + fhi(a[t].b) * w0.w
                 + flo(a[t].c) * w1.x + fhi(a[t].c) * w1.y
                 + flo(a[t].d) * w1.z + fhi(a[t].d) * w1.w;
        }
        if (s < 3) {
            const char* xr = xbytes + (size_t)(rowbase + (s + 1) * 32 + warp) * (FDIM * 4);
#pragma unroll
            for (int t = 0; t < 4; ++t) a[t] = ldg_pin32(xr + (t * 32 + lane) * 32);
        }
#pragma unroll
        for (int off = 16; off; off >>= 1)
            acc += __shfl_xor_sync(0xffffffffu, acc, off);
        if (lane == 0) s_row[s][warp] = acc;
        __syncthreads();

        const float4 v0 = reinterpret_cast<const float4*>(s_row[s])[col2 * 2];
        const float4 v1 = reinterpret_cast<const float4*>(s_row[s])[col2 * 2 + 1];
        const unsigned vbase = obase + ((unsigned)s << 3);
#pragma unroll
        for (int it = 0; it < 4; ++it) {
            unsigned q = (unsigned)it * 256u + (unsigned)warp * 8u + (unsigned)qoff;
            stg_pin32(out4 + vbase + q * (FDIM / 4) + (unsigned)(col2 * 2), v0, v1);
        }
    }
}

extern "C" void kernel_launch(void* const* d_in, const int* in_sizes, int n_in,
                              void* d_out, int out_size) {
    const float* x       = (const float*)d_in[0];  // [B,F,F]
    const float* w_value = (const float*)d_in[4];  // [D,F]
    float* out = (float*)d_out;                    // [B,F,F]
    (void)in_sizes; (void)n_in; (void)out_size;

    k_wsum<<<32, 256>>>(w_value);

    cudaLaunchConfig_t cfg = {};
    cfg.gridDim  = dim3(BDIM * (FDIM / 128));
    cfg.blockDim = dim3(1024);
    cfg.dynamicSmemBytes = 0;
    cfg.stream = 0;
    cudaLaunchAttribute attr[1];
    attr[0].id = cudaLaunchAttributeProgrammaticStreamSerialization;
    attr[0].val.programmaticStreamSerializationAllowed = 1;
    cfg.attrs = attr;
    cfg.numAttrs = 1;
    cudaLaunchKernelEx(&cfg, k_fused, x, out);
}

// round 16
// speedup vs baseline: 1.1651x; 1.1651x over previous
#include <cuda_runtime.h>
#include <cstdint>

// StochasticAttention collapses algebraically:
//   attention[b,q,v] = sum_f x[b,v,f] * (sum_d w_value[d,f])   (independent of q)
//
// R14 structure (best, 24.6us): PDL pair, x loads L2::evict_last, out stores
// L2::evict_first, interleaved sub-chunks. R16 change: attach a per-launch
// access-policy window (Persisting over x, Streaming misses) — the strong form
// of the hint pair — so x stays L2-resident across graph replays and steady-state
// DRAM traffic drops toward a pure 64MB write stream.

#define FDIM 1024
#define BDIM 16
#define DDIM 64

__device__ __align__(16) float g_wsum[FDIM];

struct U4 { uint64_t a, b, c, d; };

__device__ __forceinline__ U4 ldg_pin32(const void* p) {
    U4 v;
    asm volatile("ld.global.nc.L2::evict_last.v4.b64 {%0,%1,%2,%3}, [%4];"
                 : "=l"(v.a), "=l"(v.b), "=l"(v.c), "=l"(v.d) : "l"(p));
    return v;
}
__device__ __forceinline__ void stg_stream32(void* p, float4 v0, float4 v1) {
    uint64_t a = ((uint64_t)__float_as_uint(v0.y) << 32) | __float_as_uint(v0.x);
    uint64_t b = ((uint64_t)__float_as_uint(v0.w) << 32) | __float_as_uint(v0.z);
    uint64_t c = ((uint64_t)__float_as_uint(v1.y) << 32) | __float_as_uint(v1.x);
    uint64_t d = ((uint64_t)__float_as_uint(v1.w) << 32) | __float_as_uint(v1.z);
    asm volatile("st.global.L2::evict_first.v4.b64 [%0], {%1,%2,%3,%4};"
                 :: "l"(p), "l"(a), "l"(b), "l"(c), "l"(d) : "memory");
}
__device__ __forceinline__ float flo(uint64_t u) { return __uint_as_float((unsigned)u); }
__device__ __forceinline__ float fhi(uint64_t u) { return __uint_as_float((unsigned)(u >> 32)); }

// ---- wsum = column-sum of w_value [D, F] (32 blocks, parallel) ----
__global__ void k_wsum(const float* __restrict__ w_value) {
    __shared__ __align__(16) float4 part[32][8];
    const int col  = threadIdx.x & 7;
    const int dg   = threadIdx.x >> 3;
    const int gcol = blockIdx.x * 8 + col;
    const float4* w4 = reinterpret_cast<const float4*>(w_value);
    float4 a = w4[(size_t)(2 * dg)     * (FDIM / 4) + gcol];
    float4 b = w4[(size_t)(2 * dg + 1) * (FDIM / 4) + gcol];
    float4 s;
    s.x = a.x + b.x; s.y = a.y + b.y; s.z = a.z + b.z; s.w = a.w + b.w;
    part[dg][col] = s;
    __syncthreads();
    if (threadIdx.x < 8) {
        float4 acc = part[0][threadIdx.x];
#pragma unroll
        for (int k = 1; k < 32; ++k) {
            float4 p = part[k][threadIdx.x];
            acc.x += p.x; acc.y += p.y; acc.z += p.z; acc.w += p.w;
        }
        reinterpret_cast<float4*>(g_wsum)[blockIdx.x * 8 + threadIdx.x] = acc;
    }
    __threadfence();
    cudaTriggerProgrammaticLaunchCompletion();
}

__global__ __launch_bounds__(1024, 1)
void k_fused(const float* __restrict__ x, float* __restrict__ out) {
    __shared__ __align__(16) float4 s_wsum[FDIM / 4];  // 4 KB
    __shared__ __align__(16) float  s_row[4][32];

    const int tid  = threadIdx.x;
    const int warp = tid >> 5;
    const int lane = tid & 31;
    const int b     = blockIdx.x >> 3;
    const int chunk = blockIdx.x & 7;

    const char* xbytes = reinterpret_cast<const char*>(x);
    const unsigned rowbase = ((unsigned)b << 10) + ((unsigned)chunk << 7);

    // ---- Prefetch sub-chunk 0 BEFORE the grid dependency sync (overlaps k_wsum) ----
    U4 a[4];
    {
        const char* xr = xbytes + (size_t)(rowbase + warp) * (FDIM * 4);
#pragma unroll
        for (int t = 0; t < 4; ++t) a[t] = ldg_pin32(xr + (t * 32 + lane) * 32);
    }

    // ---- Wait for k_wsum, then pull 4KB g_wsum into shared ----
    cudaGridDependencySynchronize();
    if (tid < FDIM / 4)
        s_wsum[tid] = reinterpret_cast<const float4*>(g_wsum)[tid];
    __syncthreads();

    // ---- Pipelined sub-chunks: 32 rows each ----
    float4* out4 = reinterpret_cast<float4*>(out);
    const int qoff = lane >> 2;
    const int col2 = lane & 3;
    const unsigned obase = ((unsigned)b << 18) + ((unsigned)chunk << 5);

#pragma unroll
    for (int s = 0; s < 4; ++s) {
        float acc = 0.f;
#pragma unroll
        for (int t = 0; t < 4; ++t) {
            const int c = t * 32 + lane;
            float4 w0 = s_wsum[2 * c];
            float4 w1 = s_wsum[2 * c + 1];
            acc += flo(a[t].a) * w0.x + fhi(a[t].a) * w0.y
                 + flo(a[t].b) * w0.z + fhi(a[t].b) * w0.w
                 + flo(a[t].c) * w1.x + fhi(a[t].c) * w1.y
                 + flo(a[t].d) * w1.z + fhi(a[t].d) * w1.w;
        }
        if (s < 3) {
            const char* xr = xbytes + (size_t)(rowbase + (s + 1) * 32 + warp) * (FDIM * 4);
#pragma unroll
            for (int t = 0; t < 4; ++t) a[t] = ldg_pin32(xr + (t * 32 + lane) * 32);
        }
#pragma unroll
        for (int off = 16; off; off >>= 1)
            acc += __shfl_xor_sync(0xffffffffu, acc, off);
        if (lane == 0) s_row[s][warp] = acc;
        __syncthreads();

        const float4 v0 = reinterpret_cast<const float4*>(s_row[s])[col2 * 2];
        const float4 v1 = reinterpret_cast<const float4*>(s_row[s])[col2 * 2 + 1];
        const unsigned vbase = obase + ((unsigned)s << 3);
#pragma unroll
        for (int it = 0; it < 4; ++it) {
            unsigned q = (unsigned)it * 256u + (unsigned)warp * 8u + (unsigned)qoff;
            stg_stream32(out4 + vbase + q * (FDIM / 4) + (unsigned)(col2 * 2), v0, v1);
        }
    }
}

extern "C" void kernel_launch(void* const* d_in, const int* in_sizes, int n_in,
                              void* d_out, int out_size) {
    const float* x       = (const float*)d_in[0];  // [B,F,F]
    const float* w_value = (const float*)d_in[4];  // [D,F]
    float* out = (float*)d_out;                    // [B,F,F]
    (void)in_sizes; (void)n_in; (void)out_size;

    k_wsum<<<32, 256>>>(w_value);

    const size_t x_bytes = (size_t)BDIM * FDIM * FDIM * sizeof(float);  // 64MB

    // Query max access-policy window (device attribute; capture-safe).
    int dev = 0;
    cudaGetDevice(&dev);
    int max_win = 0;
    cudaDeviceGetAttribute(&max_win, cudaDevAttrMaxAccessPolicyWindowSize, dev);

    cudaLaunchConfig_t cfg = {};
    cfg.gridDim  = dim3(BDIM * (FDIM / 128));
    cfg.blockDim = dim3(1024);
    cfg.dynamicSmemBytes = 0;
    cfg.stream = 0;

    cudaLaunchAttribute attrs[2];
    int n_attrs = 0;

    attrs[n_attrs].id = cudaLaunchAttributeProgrammaticStreamSerialization;
    attrs[n_attrs].val.programmaticStreamSerializationAllowed = 1;
    ++n_attrs;

    if (max_win > 0) {
        size_t win = x_bytes < (size_t)max_win ? x_bytes : (size_t)max_win;
        cudaAccessPolicyWindow w = {};
        w.base_ptr  = (void*)x;
        w.num_bytes = win;
        // Scale hitRatio so the persisting set fits the granted window.
        w.hitRatio  = (float)((double)win / (double)x_bytes);
        w.hitProp   = cudaAccessPropertyPersisting;
        w.missProp  = cudaAccessPropertyStreaming;
        attrs[n_attrs].id = cudaLaunchAttributeAccessPolicyWindow;
        attrs[n_attrs].val.accessPolicyWindow = w;
        ++n_attrs;
    }

    cfg.attrs = attrs;
    cfg.numAttrs = n_attrs;
    cudaError_t err = cudaLaunchKernelEx(&cfg, k_fused, x, out);
    if (err != cudaSuccess) {
        // Fallback 1: PDL only (exact R14 behavior).
        cudaGetLastError();
        cfg.numAttrs = 1;
        err = cudaLaunchKernelEx(&cfg, k_fused, x, out);
        if (err != cudaSuccess) {
            // Fallback 2: plain launch.
            cudaGetLastError();
            k_fused<<<BDIM * (FDIM / 128), 1024>>>(x, out);
        }
    }
}